// round 16
// baseline (speedup 1.0000x reference)
#include <cuda_runtime.h>
#include <cuda_bf16.h>
#include <cstdint>

// ---------------- problem constants ----------------
#define NXC 256
#define NYC 256
#define BC  8
#define CO  32

__device__ __constant__ float c_VX    = 0.3125f;          // 1/3.2
__device__ __constant__ float c_VY    = 0.3125f;
__device__ __constant__ float c_XOFF  = -39.84375f;       // VX/2 + X_MIN
__device__ __constant__ float c_YOFF  = -19.84375f;       // VY/2 + Y_MIN

// ---------------- scratch (device globals, zero-init at load) ----------------
__device__ float g_featA[60000 * 64];
__device__ float g_featR[80000 * 64];
__device__ int   g_ownerA[BC * NYC * NXC];
__device__ int   g_ownerR[BC * NYC * NXC];

// ---------------- packed f32x2 helpers (FFMA2 via PTX, sm_100+) -------------
typedef unsigned long long ull;

__device__ __forceinline__ ull pack2(float lo, float hi) {
    ull r; asm("mov.b64 %0, {%1,%2};" : "=l"(r) : "f"(lo), "f"(hi)); return r;
}
__device__ __forceinline__ void fma2(ull& d, ull a, ull b) {
    asm("fma.rn.f32x2 %0, %1, %2, %3;" : "=l"(d) : "l"(a), "l"(b), "l"(d));
}
__device__ __forceinline__ void add2(ull& d, ull a) {
    asm("add.rn.f32x2 %0, %1, %2;" : "=l"(d) : "l"(d), "l"(a));
}
__device__ __forceinline__ float2 unpack2(ull v) {
    float2 r; asm("mov.b64 {%0,%1}, %2;" : "=f"(r.x), "=f"(r.y) : "l"(v)); return r;
}
__device__ __forceinline__ void red_add_v4(float* p, float a, float b, float c, float d) {
    asm volatile("red.global.add.v4.f32 [%0], {%1,%2,%3,%4};"
                 :: "l"(p), "f"(a), "f"(b), "f"(c), "f"(d) : "memory");
}

// ============================================================================
// VFE multi-pillar warp body, software-pipelined, NO shuffle reduction.
// ONE WARP handles NP consecutive pillars; folded weights built once per warp.
// Voxel rows loaded as ONE LDG.128 per lane; next pillar's float4 prefetched
// during current compute. Lane owns output-dim pair d = (2*lane, 2*lane+1).
//   dot'_p = sum_{c<C} v_pc * we_c + K0        (K0 = b - xo*wC3 - yo*wC4)
//   out    = max(0, max_p dot'_p - mcorr),  mcorr = (S·(wC0,wC1,wC2))/np
// where S = sum_{p<np} xyz_p is accumulated with FADD2 inside the dot loop
// (mcorr is p-invariant so it commutes with the max; relu applied after).
// Owner resolution (last idx wins) fused via idempotent atomicMax.
// ============================================================================
template <int P, int C, int NP>
__device__ __forceinline__ void vfe_multi(
    const float* __restrict__ voxels, const int* __restrict__ coors,
    const int* __restrict__ nump, const float* __restrict__ W,
    const float* __restrict__ bias, float* __restrict__ outf,
    int* __restrict__ owner, int base, int M, ull* __restrict__ sraw)
{
    constexpr int PC  = P * C;
    constexpr int PC4 = PC / 4;       // 25 (agent) or 24 (rg)
    int lane = threadIdx.x & 31;

    // ---- per-warp weight fold (amortized over NP pillars) ----
    float2 wc[5];                       // channels C..C+4
#pragma unroll
    for (int c = 0; c < 5; ++c) wc[c] = *(const float2*)(W + (C + c) * 64 + 2 * lane);
    float2 bs = *(const float2*)(bias + 2 * lane);

    ull we2[C];
#pragma unroll
    for (int c = 0; c < C; ++c) {
        float2 w = *(const float2*)(W + c * 64 + 2 * lane);
        if (c == 0) { w.x += wc[0].x + wc[3].x;  w.y += wc[0].y + wc[3].y; }
        if (c == 1) { w.x += wc[1].x + wc[4].x;  w.y += wc[1].y + wc[4].y; }
        if (c == 2) { w.x += wc[2].x;            w.y += wc[2].y; }
        we2[c] = pack2(w.x, w.y);
    }

    // prologue prefetch: pillar 'base' row into registers (LDG.128)
    float4 nv = make_float4(0.f, 0.f, 0.f, 0.f);
    if (base < M && lane < PC4)
        nv = *(const float4*)(voxels + (size_t)base * PC + lane * 4);

#pragma unroll 1
    for (int t = 0; t < NP; ++t) {
        int i = base + t;                 // warp-uniform
        if (i >= M) return;

        // stage current pillar from prefetch regs (duplicated pairs)
        if (lane < PC4) {
            sraw[lane * 4 + 0] = pack2(nv.x, nv.x);
            sraw[lane * 4 + 1] = pack2(nv.y, nv.y);
            sraw[lane * 4 + 2] = pack2(nv.z, nv.z);
            sraw[lane * 4 + 3] = pack2(nv.w, nv.w);
        }
        int np = nump[i];                 // 1..P
        __syncwarp();

        // prefetch next pillar while this one computes
        if (t + 1 < NP && i + 1 < M && lane < PC4)
            nv = *(const float4*)(voxels + (size_t)(i + 1) * PC + lane * 4);

        int cb = coors[3 * i], cy = coors[3 * i + 1], cx = coors[3 * i + 2];
        if (lane == 0) atomicMax(&owner[(cb * NYC + cy) * NXC + cx], i + 1);
        float xo = (float)cx * c_VX + c_XOFF;
        float yo = (float)cy * c_VY + c_YOFF;

        float Kx = bs.x - xo * wc[3].x - yo * wc[4].x;
        float Ky = bs.y - xo * wc[3].y - yo * wc[4].y;
        ull K2 = pack2(Kx, Ky);

        ull S0 = 0, S1 = 0, S2 = 0;       // dup-pair xyz sums
        float a0 = -3.0e38f, a1 = -3.0e38f, b0 = -3.0e38f, b1 = -3.0e38f;
        int p = 0;
        for (; p + 2 <= np; p += 2) {
            ull d2 = K2, e2 = K2;
            const ull* r0 = &sraw[p * C];
#pragma unroll
            for (int c = 0; c < C; ++c) {
                fma2(d2, r0[c],     we2[c]);
                fma2(e2, r0[C + c], we2[c]);
            }
            add2(S0, r0[0]); add2(S1, r0[1]); add2(S2, r0[2]);
            add2(S0, r0[C]); add2(S1, r0[C + 1]); add2(S2, r0[C + 2]);
            float2 u = unpack2(d2), w = unpack2(e2);
            a0 = fmaxf(a0, u.x); a1 = fmaxf(a1, u.y);
            b0 = fmaxf(b0, w.x); b1 = fmaxf(b1, w.y);
        }
        if (p < np) {
            ull d2 = K2;
            const ull* r0 = &sraw[p * C];
#pragma unroll
            for (int c = 0; c < C; ++c) fma2(d2, r0[c], we2[c]);
            add2(S0, r0[0]); add2(S1, r0[1]); add2(S2, r0[2]);
            float2 u = unpack2(d2);
            a0 = fmaxf(a0, u.x); a1 = fmaxf(a1, u.y);
        }
        float inv = 1.f / (float)np;
        float Sx = unpack2(S0).x, Sy = unpack2(S1).x, Sz = unpack2(S2).x;
        float mcx = (Sx * wc[0].x + Sy * wc[1].x + Sz * wc[2].x) * inv;
        float mcy = (Sx * wc[0].y + Sy * wc[1].y + Sz * wc[2].y) * inv;
        float2 res = make_float2(fmaxf(0.f, fmaxf(a0, b0) - mcx),
                                 fmaxf(0.f, fmaxf(a1, b1) - mcy));
        *(float2*)(outf + (size_t)i * 64 + 2 * lane) = res;
        __syncwarp();                     // protect sraw before next staging
    }
}

// ============================================================================
// Fused prep kernel: [init blocks | VFE agent blocks | VFE rg blocks]
// 256 threads = 8 warps; each warp handles NPIL consecutive pillars.
// ============================================================================
#define INITB 1024
#define NPIL  8

__global__ __launch_bounds__(256) void prep_kernel(
    const float* voxA, const int* cA, const int* npA, const float* wA, const float* bA,
    const float* voxR, const int* cR, const int* npR, const float* wR, const float* bR,
    float* featA, float* featR, int* ownerA, int* ownerR, int Ma, int Mr, int blkA,
    float4* out4, const float* __restrict__ cb, int n4)
{
    __shared__ __align__(16) ull sraw[8][100];   // max P*C = 100

    int bid = blockIdx.x;
    if (bid < INITB) {
        for (int i = bid * 256 + threadIdx.x; i < n4; i += INITB * 256) {
            int c = (i * 4) & (CO - 1);
            out4[i] = make_float4(cb[c], cb[c + 1], cb[c + 2], cb[c + 3]);
        }
        return;
    }
    int warp = threadIdx.x >> 5;
    int rel = bid - INITB;
    if (rel < blkA) {
        int base = (rel * 8 + warp) * NPIL;
        vfe_multi<20, 5, NPIL>(voxA, cA, npA, wA, bA, featA, ownerA, base, Ma, sraw[warp]);
    } else {
        int base = ((rel - blkA) * 8 + warp) * NPIL;
        vfe_multi<32, 3, NPIL>(voxR, cR, npR, wR, bR, featR, ownerR, base, Mr, sraw[warp]);
    }
}

// ============================================================================
// Fused sparse scatter-conv, all 9 taps, co-QUAD lanes + red.v4 epilogue.
// Block 256 thr (8 warps), T=8 pillars/warp.
// Lane map: g = lane&7 -> co quad c4 = 4g;  q = lane>>3 -> pillar slot.
// Lane accumulates 4 co per tap for pillars t = q and t = q+4:
//   acc[s][tap][0..1]  (2 ull = 4 floats), s = t>>2.
// Inner loop per ci: 9 LDS.128 (weights, 128B distinct per tap) + 2 LDS.32
// broadcast (features) + 2 pack + 36 FFMA2 (fma work invariant vs R10).
// Epilogue: red.global.add.v4.f32 — one warp instr covers 4 pillars x 1 tap,
// HALF the red instrs and HALF the red lane-count of the v2 scheme.
// smem: 72 KB weights + 18 KB features = 90 KB -> 2 CTA/SM.
// ============================================================================
#define CONV_SMEM (9 * 64 * 32 * 4 + 8 * 64 * 9 * 4)

__global__ __launch_bounds__(256, 2) void conv_kernel(
    const float* __restrict__ fA, const int* __restrict__ cA, const int* __restrict__ oA, int Ma,
    const float* __restrict__ fR, const int* __restrict__ cR, const int* __restrict__ oR, int Mr,
    const float* __restrict__ conv_w, float* __restrict__ out, int Ga, int Gr)
{
    extern __shared__ __align__(16) float smem[];
    float* sw = smem;                 // [tap][ci][co]
    float* sf = smem + 9 * 64 * 32;   // [warp][ci][t(stride 9)]

    bool isA = (int)blockIdx.x < Ga;
    const float* feats = isA ? fA : fR;
    const int*   coors = isA ? cA : cR;
    const int*   owner = isA ? oA : oR;
    int M      = isA ? Ma : Mr;
    int ci_off = isA ? 0 : 64;
    int nblk   = isA ? Ga : Gr;
    int blk    = isA ? blockIdx.x : blockIdx.x - Ga;

    int tid = threadIdx.x;
    for (int k = tid; k < 9 * 64 * 32; k += 256) {
        int tap = k >> 11, rem = k & 2047;              // rem = ci*32+co
        sw[k] = conv_w[(tap * 128 + ci_off + (rem >> 5)) * 32 + (rem & 31)];
    }
    __syncthreads();

    int warp = tid >> 5, lane = tid & 31;
    int g  = lane & 7;                 // co-quad index
    int q  = lane >> 3;                // pillar slot (0..3)
    int c4 = g * 4;
    float* sfw = sf + warp * (64 * 9);

    int stride = nblk * 8 * 8;         // blocks * warps * T
    for (int base = (blk * 8 + warp) * 8; base < M; base += stride) {
        int mycell[2]; bool myv[2];
#pragma unroll
        for (int t = 0; t < 8; ++t) {
            int i = base + t;
            float f0 = 0.f, f1 = 0.f;
            if (i < M) {
                f0 = feats[(size_t)i * 64 + lane];
                f1 = feats[(size_t)i * 64 + 32 + lane];
            }
            sfw[lane * 9 + t]        = f0;   // stride 9 -> conflict-free
            sfw[(lane + 32) * 9 + t] = f1;
            if ((t & 3) == q) {              // this lane owns pillar t
                int s = t >> 2;
                bool v = false; int cell = 0;
                if (i < M) {
                    int bb = coors[3 * i], y = coors[3 * i + 1], x = coors[3 * i + 2];
                    cell = (bb * NYC + y) * NXC + x;
                    v = (owner[cell] == i + 1);
                }
                mycell[s] = cell; myv[s] = v;
            }
        }
        __syncwarp();

        ull acc[2][9][2];
#pragma unroll
        for (int s = 0; s < 2; ++s)
#pragma unroll
            for (int k = 0; k < 9; ++k) { acc[s][k][0] = 0ULL; acc[s][k][1] = 0ULL; }

#pragma unroll 4
        for (int ci = 0; ci < 64; ++ci) {
            float fa = sfw[ci * 9 + q];          // pillar t = q
            float fb = sfw[ci * 9 + 4 + q];      // pillar t = q+4
            ull f2a = pack2(fa, fa), f2b = pack2(fb, fb);
            const float* wbase = sw + ci * 32 + c4;
#pragma unroll
            for (int tap = 0; tap < 9; ++tap) {
                ulonglong2 w2 = *(const ulonglong2*)(wbase + tap * 2048);  // LDS.128
                fma2(acc[0][tap][0], f2a, w2.x);
                fma2(acc[0][tap][1], f2a, w2.y);
                fma2(acc[1][tap][0], f2b, w2.x);
                fma2(acc[1][tap][1], f2b, w2.y);
            }
        }

#pragma unroll
        for (int s = 0; s < 2; ++s) {
            if (!myv[s]) continue;
            int cell = mycell[s];
            int x = cell & 255, y = (cell >> 8) & 255, bt = cell >> 16;
#pragma unroll
            for (int ky = 0; ky < 3; ++ky) {
                int oy = y + 1 - ky;
                if ((unsigned)oy >= NYC) continue;
                size_t rb = ((size_t)bt * NYC + oy) * NXC;
#pragma unroll
                for (int kx = 0; kx < 3; ++kx) {
                    int ox = x + 1 - kx;
                    if ((unsigned)ox >= NXC) continue;
                    float2 lo = unpack2(acc[s][ky * 3 + kx][0]);
                    float2 hi = unpack2(acc[s][ky * 3 + kx][1]);
                    red_add_v4(out + (rb + ox) * 32 + c4, lo.x, lo.y, hi.x, hi.y);
                }
            }
        }
        __syncwarp();   // all lanes done reading sfw before next overwrite
    }
}

// ============================================================================
// launch
// ============================================================================
extern "C" void kernel_launch(void* const* d_in, const int* in_sizes, int n_in,
                              void* d_out, int out_size)
{
    const float* voxels_agent = (const float*)d_in[0];
    const int*   coors_agent  = (const int*)  d_in[1];
    const int*   np_agent     = (const int*)  d_in[2];
    const float* voxels_rg    = (const float*)d_in[3];
    const int*   coors_rg     = (const int*)  d_in[4];
    const int*   np_rg        = (const int*)  d_in[5];
    const float* w_agent      = (const float*)d_in[6];
    const float* b_agent      = (const float*)d_in[7];
    const float* w_rg         = (const float*)d_in[8];
    const float* b_rg         = (const float*)d_in[9];
    const float* conv_w       = (const float*)d_in[10];
    const float* conv_b       = (const float*)d_in[11];

    int Ma = in_sizes[0] / (20 * 5);
    int Mr = in_sizes[3] / (32 * 3);
    float* out = (float*)d_out;

    float *featA, *featR;
    int   *ownerA, *ownerR;
    cudaGetSymbolAddress((void**)&featA,  g_featA);
    cudaGetSymbolAddress((void**)&featR,  g_featR);
    cudaGetSymbolAddress((void**)&ownerA, g_ownerA);
    cudaGetSymbolAddress((void**)&ownerR, g_ownerR);

    // 1) fused init + pipelined multi-pillar VFE + owner resolution
    int n4 = out_size / 4;
    int blkA = (Ma + 8 * NPIL - 1) / (8 * NPIL);
    int blkR = (Mr + 8 * NPIL - 1) / (8 * NPIL);
    prep_kernel<<<INITB + blkA + blkR, 256>>>(
        voxels_agent, coors_agent, np_agent, w_agent, b_agent,
        voxels_rg, coors_rg, np_rg, w_rg, b_rg,
        featA, featR, ownerA, ownerR, Ma, Mr, blkA,
        (float4*)out, conv_b, n4);

    // 2) fused sparse scatter-conv (both sets, all 9 taps, red.v4 epilogue)
    cudaFuncSetAttribute(conv_kernel, cudaFuncAttributeMaxDynamicSharedMemorySize, CONV_SMEM);
    int total = Ma + Mr;
    int G = 296;                               // 2 CTAs/SM on 148 SMs
    int Ga = (int)((long long)G * Ma / total);
    if (Ga < 1) Ga = 1; if (Ga > G - 1) Ga = G - 1;
    int Gr = G - Ga;
    conv_kernel<<<G, 256, CONV_SMEM>>>(featA, coors_agent, ownerA, Ma,
                                       featR, coors_rg,    ownerR, Mr,
                                       conv_w, out, Ga, Gr);
}

// round 17
// speedup vs baseline: 1.4328x; 1.4328x over previous
#include <cuda_runtime.h>
#include <cuda_bf16.h>
#include <cstdint>

// ---------------- problem constants ----------------
#define NXC 256
#define NYC 256
#define BC  8
#define CO  32

__device__ __constant__ float c_VX    = 0.3125f;          // 1/3.2
__device__ __constant__ float c_VY    = 0.3125f;
__device__ __constant__ float c_XOFF  = -39.84375f;       // VX/2 + X_MIN
__device__ __constant__ float c_YOFF  = -19.84375f;       // VY/2 + Y_MIN

// ---------------- scratch (device globals, zero-init at load) ----------------
__device__ float g_featA[60000 * 64];
__device__ float g_featR[80000 * 64];
__device__ int   g_ownerA[BC * NYC * NXC];
__device__ int   g_ownerR[BC * NYC * NXC];

// ---------------- packed f32x2 helpers (FFMA2 via PTX, sm_100+) -------------
typedef unsigned long long ull;

__device__ __forceinline__ ull pack2(float lo, float hi) {
    ull r; asm("mov.b64 %0, {%1,%2};" : "=l"(r) : "f"(lo), "f"(hi)); return r;
}
__device__ __forceinline__ void fma2(ull& d, ull a, ull b) {
    asm("fma.rn.f32x2 %0, %1, %2, %3;" : "=l"(d) : "l"(a), "l"(b), "l"(d));
}
__device__ __forceinline__ float2 unpack2(ull v) {
    float2 r; asm("mov.b64 {%0,%1}, %2;" : "=f"(r.x), "=f"(r.y) : "l"(v)); return r;
}
__device__ __forceinline__ void red_add_v2(float* p, float x, float y) {
    asm volatile("red.global.add.v2.f32 [%0], {%1,%2};" :: "l"(p), "f"(x), "f"(y) : "memory");
}

// ============================================================================
// VFE multi-pillar warp body (R15-proven form: shuffle mean + LDG.128 pipeline).
// ONE WARP handles NP consecutive pillars; folded weights built once per warp.
// Lane owns output-dim pair d = (2*lane, 2*lane+1).
//   dot_p = sum_{c<C} v_pc * we_c + K     (cluster/center channels folded)
// out = max(0, max_{p<np} dot_p). Owner resolution (last idx wins) fused.
// ============================================================================
template <int P, int C, int NP>
__device__ __forceinline__ void vfe_multi(
    const float* __restrict__ voxels, const int* __restrict__ coors,
    const int* __restrict__ nump, const float* __restrict__ W,
    const float* __restrict__ bias, float* __restrict__ outf,
    int* __restrict__ owner, int base, int M, ull* __restrict__ sraw)
{
    constexpr int PC  = P * C;
    constexpr int PC4 = PC / 4;       // 25 (agent) or 24 (rg)
    int lane = threadIdx.x & 31;

    // ---- per-warp weight fold (amortized over NP pillars) ----
    float2 wc[5];                       // channels C..C+4
#pragma unroll
    for (int c = 0; c < 5; ++c) wc[c] = *(const float2*)(W + (C + c) * 64 + 2 * lane);
    float2 bs = *(const float2*)(bias + 2 * lane);

    ull we2[C];
#pragma unroll
    for (int c = 0; c < C; ++c) {
        float2 w = *(const float2*)(W + c * 64 + 2 * lane);
        if (c == 0) { w.x += wc[0].x + wc[3].x;  w.y += wc[0].y + wc[3].y; }
        if (c == 1) { w.x += wc[1].x + wc[4].x;  w.y += wc[1].y + wc[4].y; }
        if (c == 2) { w.x += wc[2].x;            w.y += wc[2].y; }
        we2[c] = pack2(w.x, w.y);
    }

    const float* srawf = (const float*)sraw;   // lo half of each dup pair

    // prologue prefetch: pillar 'base' row into registers (LDG.128)
    float4 nv = make_float4(0.f, 0.f, 0.f, 0.f);
    if (base < M && lane < PC4)
        nv = *(const float4*)(voxels + (size_t)base * PC + lane * 4);

#pragma unroll 1
    for (int t = 0; t < NP; ++t) {
        int i = base + t;                 // warp-uniform
        if (i >= M) return;

        // stage current pillar from prefetch regs (duplicated pairs)
        if (lane < PC4) {
            sraw[lane * 4 + 0] = pack2(nv.x, nv.x);
            sraw[lane * 4 + 1] = pack2(nv.y, nv.y);
            sraw[lane * 4 + 2] = pack2(nv.z, nv.z);
            sraw[lane * 4 + 3] = pack2(nv.w, nv.w);
        }
        int np = nump[i];                 // 1..P
        __syncwarp();

        // prefetch next pillar while this one computes
        if (t + 1 < NP && i + 1 < M && lane < PC4)
            nv = *(const float4*)(voxels + (size_t)(i + 1) * PC + lane * 4);

        // mean over first np points (P <= 32) via bfly reduction
        float sx = 0.f, sy = 0.f, sz = 0.f;
        if (lane < np) {
            sx = srawf[(lane * C + 0) * 2];
            sy = srawf[(lane * C + 1) * 2];
            sz = srawf[(lane * C + 2) * 2];
        }
#pragma unroll
        for (int o = 16; o; o >>= 1) {
            sx += __shfl_xor_sync(0xffffffffu, sx, o);
            sy += __shfl_xor_sync(0xffffffffu, sy, o);
            sz += __shfl_xor_sync(0xffffffffu, sz, o);
        }
        float inv = 1.f / (float)np;
        float mx = sx * inv, my = sy * inv, mz = sz * inv;

        int cb = coors[3 * i], cy = coors[3 * i + 1], cx = coors[3 * i + 2];
        if (lane == 0) atomicMax(&owner[(cb * NYC + cy) * NXC + cx], i + 1);
        float xo = (float)cx * c_VX + c_XOFF;
        float yo = (float)cy * c_VY + c_YOFF;

        float Kx = bs.x - mx * wc[0].x - my * wc[1].x - mz * wc[2].x
                        - xo * wc[3].x - yo * wc[4].x;
        float Ky = bs.y - mx * wc[0].y - my * wc[1].y - mz * wc[2].y
                        - xo * wc[3].y - yo * wc[4].y;
        ull K2 = pack2(Kx, Ky);

        float a0 = 0.f, a1 = 0.f, b0 = 0.f, b1 = 0.f;
        int p = 0;
        for (; p + 2 <= np; p += 2) {
            ull d2 = K2, e2 = K2;
            const ull* r0 = &sraw[p * C];
#pragma unroll
            for (int c = 0; c < C; ++c) {
                fma2(d2, r0[c],     we2[c]);
                fma2(e2, r0[C + c], we2[c]);
            }
            float2 u = unpack2(d2), w = unpack2(e2);
            a0 = fmaxf(a0, u.x); a1 = fmaxf(a1, u.y);
            b0 = fmaxf(b0, w.x); b1 = fmaxf(b1, w.y);
        }
        if (p < np) {
            ull d2 = K2;
            const ull* r0 = &sraw[p * C];
#pragma unroll
            for (int c = 0; c < C; ++c) fma2(d2, r0[c], we2[c]);
            float2 u = unpack2(d2);
            a0 = fmaxf(a0, u.x); a1 = fmaxf(a1, u.y);
        }
        float2 res = make_float2(fmaxf(a0, b0), fmaxf(a1, b1));
        *(float2*)(outf + (size_t)i * 64 + 2 * lane) = res;
        __syncwarp();                     // protect sraw before next staging
    }
}

// ============================================================================
// Fused prep kernel: [init blocks | VFE agent blocks | VFE rg blocks]
// ============================================================================
#define INITB 1024
#define NPIL  8

__global__ __launch_bounds__(256) void prep_kernel(
    const float* voxA, const int* cA, const int* npA, const float* wA, const float* bA,
    const float* voxR, const int* cR, const int* npR, const float* wR, const float* bR,
    float* featA, float* featR, int* ownerA, int* ownerR, int Ma, int Mr, int blkA,
    float4* out4, const float* __restrict__ cb, int n4)
{
    __shared__ __align__(16) ull sraw[8][100];   // max P*C = 100

    int bid = blockIdx.x;
    if (bid < INITB) {
        for (int i = bid * 256 + threadIdx.x; i < n4; i += INITB * 256) {
            int c = (i * 4) & (CO - 1);
            out4[i] = make_float4(cb[c], cb[c + 1], cb[c + 2], cb[c + 3]);
        }
        return;
    }
    int warp = threadIdx.x >> 5;
    int rel = bid - INITB;
    if (rel < blkA) {
        int base = (rel * 8 + warp) * NPIL;
        vfe_multi<20, 5, NPIL>(voxA, cA, npA, wA, bA, featA, ownerA, base, Ma, sraw[warp]);
    } else {
        int base = ((rel - blkA) * 8 + warp) * NPIL;
        vfe_multi<32, 3, NPIL>(voxR, cR, npR, wR, bR, featR, ownerR, base, Mr, sraw[warp]);
    }
}

// ============================================================================
// Fused sparse scatter-conv (R10 inner loop, LDS.64 weights, red.v2 epilogue)
// with re-permuted feature staging:
//   sf row layout per ci: [h][tp] (8 floats, 16B-aligned groups) so each lane
//   reads its 4 pillar features as ONE LDS.128 per ci (was 4x LDS.32), and
//   staging is 4x STS.128 from registers (was 16x STS.32).
// Block 256 thr (8 warps), T=8 pillars/warp. Lane: c2=2*(lane&15) co-pair,
// h=lane>>4 pillar parity (owns pillars t with t&1==h, tp=t>>1).
// Weights: sw[tap][ci][co], 9 LDS.64/ci (16 distinct 8B = 128B = 1 wf each,
// crossbar minimum). Epilogue: red.global.add.v2.f32.
// smem: 72 KB weights + 8 warps * 64 rows * 8 floats = 16 KB -> 88 KB, 2 CTA/SM.
// ============================================================================
#define SF_ROW 8
#define CONV_SMEM (9 * 64 * 32 * 4 + 8 * 64 * SF_ROW * 4)

__global__ __launch_bounds__(256, 2) void conv_kernel(
    const float* __restrict__ fA, const int* __restrict__ cA, const int* __restrict__ oA, int Ma,
    const float* __restrict__ fR, const int* __restrict__ cR, const int* __restrict__ oR, int Mr,
    const float* __restrict__ conv_w, float* __restrict__ out, int Ga, int Gr)
{
    extern __shared__ __align__(16) float smem[];
    float* sw = smem;                 // [tap][ci][co]
    float* sf = smem + 9 * 64 * 32;   // [warp][ci(64)][h(2)][tp(4)]

    bool isA = (int)blockIdx.x < Ga;
    const float* feats = isA ? fA : fR;
    const int*   coors = isA ? cA : cR;
    const int*   owner = isA ? oA : oR;
    int M      = isA ? Ma : Mr;
    int ci_off = isA ? 0 : 64;
    int nblk   = isA ? Ga : Gr;
    int blk    = isA ? blockIdx.x : blockIdx.x - Ga;

    int tid = threadIdx.x;
    for (int k = tid; k < 9 * 64 * 32; k += 256) {
        int tap = k >> 11, rem = k & 2047;              // rem = ci*32+co
        sw[k] = conv_w[(tap * 128 + ci_off + (rem >> 5)) * 32 + (rem & 31)];
    }
    __syncthreads();

    int warp = tid >> 5, lane = tid & 31;
    int h = lane >> 4;                 // pillar parity this lane owns
    int c2 = (lane & 15) * 2;          // co pair
    float* sfw = sf + warp * (64 * SF_ROW);

    int stride = nblk * 8 * 8;         // blocks * warps * T
    for (int base = (blk * 8 + warp) * 8; base < M; base += stride) {
        int mycell[4]; bool myv[4];
        float r0[8], r1[8];
#pragma unroll
        for (int t = 0; t < 8; ++t) {
            int i = base + t;
            float f0 = 0.f, f1 = 0.f;
            if (i < M) {
                f0 = feats[(size_t)i * 64 + lane];
                f1 = feats[(size_t)i * 64 + 32 + lane];
            }
            int pp = (t & 1) * 4 + (t >> 1);   // row position [h][tp]
            r0[pp] = f0; r1[pp] = f1;
            if ((t & 1) == h) {
                int tp = t >> 1;
                bool v = false; int cell = 0;
                if (i < M) {
                    int bb = coors[3 * i], y = coors[3 * i + 1], x = coors[3 * i + 2];
                    cell = (bb * NYC + y) * NXC + x;
                    v = (owner[cell] == i + 1);
                }
                mycell[tp] = cell; myv[tp] = v;
            }
        }
        // 4x STS.128, rows 32B apart -> distinct addresses, minimal phases
        *(float4*)(sfw + lane * SF_ROW)            = make_float4(r0[0], r0[1], r0[2], r0[3]);
        *(float4*)(sfw + lane * SF_ROW + 4)        = make_float4(r0[4], r0[5], r0[6], r0[7]);
        *(float4*)(sfw + (lane + 32) * SF_ROW)     = make_float4(r1[0], r1[1], r1[2], r1[3]);
        *(float4*)(sfw + (lane + 32) * SF_ROW + 4) = make_float4(r1[4], r1[5], r1[6], r1[7]);
        __syncwarp();

        ull acc[4][9];
#pragma unroll
        for (int tp = 0; tp < 4; ++tp)
#pragma unroll
            for (int k = 0; k < 9; ++k) acc[tp][k] = 0ULL;

#pragma unroll 4
        for (int ci = 0; ci < 64; ++ci) {
            // one LDS.128: this lane's 4 pillar features (parity h)
            float4 fv = *(const float4*)(sfw + ci * SF_ROW + h * 4);
            ull f2[4] = { pack2(fv.x, fv.x), pack2(fv.y, fv.y),
                          pack2(fv.z, fv.z), pack2(fv.w, fv.w) };
            const float* wrow = sw + ci * 32 + c2;
#pragma unroll
            for (int tap = 0; tap < 9; ++tap) {
                ull w2 = *reinterpret_cast<const ull*>(wrow + tap * 2048);  // LDS.64 pair
#pragma unroll
                for (int tp = 0; tp < 4; ++tp) fma2(acc[tp][tap], f2[tp], w2);
            }
        }

#pragma unroll
        for (int tp = 0; tp < 4; ++tp) {
            if (!myv[tp]) continue;
            int cell = mycell[tp];
            int x = cell & 255, y = (cell >> 8) & 255, bt = cell >> 16;
#pragma unroll
            for (int ky = 0; ky < 3; ++ky) {
                int oy = y + 1 - ky;
                if ((unsigned)oy >= NYC) continue;
                size_t rb = ((size_t)bt * NYC + oy) * NXC;
#pragma unroll
                for (int kx = 0; kx < 3; ++kx) {
                    int ox = x + 1 - kx;
                    if ((unsigned)ox >= NXC) continue;
                    float2 v2 = unpack2(acc[tp][ky * 3 + kx]);
                    red_add_v2(out + (rb + ox) * 32 + c2, v2.x, v2.y);
                }
            }
        }
        __syncwarp();   // all lanes done reading sfw before next overwrite
    }
}

// ============================================================================
// launch
// ============================================================================
extern "C" void kernel_launch(void* const* d_in, const int* in_sizes, int n_in,
                              void* d_out, int out_size)
{
    const float* voxels_agent = (const float*)d_in[0];
    const int*   coors_agent  = (const int*)  d_in[1];
    const int*   np_agent     = (const int*)  d_in[2];
    const float* voxels_rg    = (const float*)d_in[3];
    const int*   coors_rg     = (const int*)  d_in[4];
    const int*   np_rg        = (const int*)  d_in[5];
    const float* w_agent      = (const float*)d_in[6];
    const float* b_agent      = (const float*)d_in[7];
    const float* w_rg         = (const float*)d_in[8];
    const float* b_rg         = (const float*)d_in[9];
    const float* conv_w       = (const float*)d_in[10];
    const float* conv_b       = (const float*)d_in[11];

    int Ma = in_sizes[0] / (20 * 5);
    int Mr = in_sizes[3] / (32 * 3);
    float* out = (float*)d_out;

    float *featA, *featR;
    int   *ownerA, *ownerR;
    cudaGetSymbolAddress((void**)&featA,  g_featA);
    cudaGetSymbolAddress((void**)&featR,  g_featR);
    cudaGetSymbolAddress((void**)&ownerA, g_ownerA);
    cudaGetSymbolAddress((void**)&ownerR, g_ownerR);

    // 1) fused init + pipelined multi-pillar VFE + owner resolution
    int n4 = out_size / 4;
    int blkA = (Ma + 8 * NPIL - 1) / (8 * NPIL);
    int blkR = (Mr + 8 * NPIL - 1) / (8 * NPIL);
    prep_kernel<<<INITB + blkA + blkR, 256>>>(
        voxels_agent, coors_agent, np_agent, w_agent, b_agent,
        voxels_rg, coors_rg, np_rg, w_rg, b_rg,
        featA, featR, ownerA, ownerR, Ma, Mr, blkA,
        (float4*)out, conv_b, n4);

    // 2) fused sparse scatter-conv (both sets, all 9 taps)
    cudaFuncSetAttribute(conv_kernel, cudaFuncAttributeMaxDynamicSharedMemorySize, CONV_SMEM);
    int total = Ma + Mr;
    int G = 296;                               // 2 CTAs/SM on 148 SMs
    int Ga = (int)((long long)G * Ma / total);
    if (Ga < 1) Ga = 1; if (Ga > G - 1) Ga = G - 1;
    int Gr = G - Ga;
    conv_kernel<<<G, 256, CONV_SMEM>>>(featA, coors_agent, ownerA, Ma,
                                       featR, coors_rg,    ownerR, Mr,
                                       conv_w, out, Ga, Gr);
}